// round 1
// baseline (speedup 1.0000x reference)
#include <cuda_runtime.h>

// Problem constants
#define S_LEN 8192
#define BATCH 8
#define DM    128            // d_model == K of QKV GEMM
#define NQKV  384            // 3*H*HD
#define MT    64             // positions per block (kernel 1)
#define TH1   512
#define RS    388            // staging row stride (floats): 4*odd -> clean LDS.128 banks
#define K1_SMEM_FLOATS (MT*DM + DM*NQKV)     // 8192 + 49152 = 57344
#define K1_SMEM_BYTES  (K1_SMEM_FLOATS*4)    // 229376 B (<= 227KB opt-in)

#define KC    16             // k sub-chunk (kernel 2)
#define NKC   16             // number of split-K chunks
#define KCH   (S_LEN/NKC)    // 512 k per block

// Scratch (device globals: allowed; no cudaMalloc anywhere)
__device__ float g_attn[BATCH * S_LEN * DM];          // 33.5 MB attention output, flat (B,S,H,hd)
__device__ float g_part[NKC * BATCH * DM * DM];       // 8 MB split-K partials

// ---------------------------------------------------------------------------
// Kernel 1: qkv = x @ W_qkv + b ; per-position HxH attention ; write flat out
// ---------------------------------------------------------------------------
__global__ __launch_bounds__(TH1, 1)
void k1_qkv_attn(const float* __restrict__ x,
                 const float* __restrict__ Wqkv,
                 const float* __restrict__ bqkv)
{
    extern __shared__ float sm[];
    float* As = sm;             // [MT][DM]      32 KB
    float* Bs = sm + MT*DM;     // [DM][NQKV]   192 KB
    float* St = sm + MT*DM;     // staging [MT][RS] aliases Bs after GEMM

    const int tid   = threadIdx.x;
    const int mbase = blockIdx.x * MT;   // global row (b*S+s) base

    // Cooperative loads (coalesced float4)
    {
        const float4* xg = (const float4*)(x + (size_t)mbase * DM);
        float4* a4 = (float4*)As;
        #pragma unroll
        for (int t = 0; t < (MT*DM/4)/TH1; t++)       // 4
            a4[tid + TH1*t] = xg[tid + TH1*t];
        const float4* wg = (const float4*)Wqkv;
        float4* b4 = (float4*)Bs;
        #pragma unroll
        for (int t = 0; t < (DM*NQKV/4)/TH1; t++)     // 24
            b4[tid + TH1*t] = wg[tid + TH1*t];
    }
    __syncthreads();

    const int tcol = tid & 63;     // column group (warp lanes consecutive -> bank clean)
    const int trow = tid >> 6;     // row group (broadcast A reads)

    float bq[6];
    #pragma unroll
    for (int j = 0; j < 6; j++) bq[j] = bqkv[tcol + 64*j];

    float acc[8][6];
    #pragma unroll
    for (int i = 0; i < 8; i++)
        #pragma unroll
        for (int j = 0; j < 6; j++) acc[i][j] = 0.f;

    #pragma unroll 2
    for (int k0 = 0; k0 < DM; k0 += 4) {
        float4 a4[8];
        #pragma unroll
        for (int i = 0; i < 8; i++)
            a4[i] = *(const float4*)&As[(trow + 8*i)*DM + k0];
        #pragma unroll
        for (int kk = 0; kk < 4; kk++) {
            float bb[6];
            #pragma unroll
            for (int j = 0; j < 6; j++)
                bb[j] = Bs[(k0 + kk)*NQKV + tcol + 64*j];
            #pragma unroll
            for (int i = 0; i < 8; i++) {
                float av = (kk == 0) ? a4[i].x : (kk == 1) ? a4[i].y
                         : (kk == 2) ? a4[i].z : a4[i].w;
                #pragma unroll
                for (int j = 0; j < 6; j++)
                    acc[i][j] = fmaf(av, bb[j], acc[i][j]);
            }
        }
    }

    __syncthreads();   // everyone done reading Bs before staging overwrites it
    #pragma unroll
    for (int i = 0; i < 8; i++)
        #pragma unroll
        for (int j = 0; j < 6; j++)
            St[(trow + 8*i)*RS + tcol + 64*j] = acc[i][j] + bq[j];
    __syncthreads();

    // Attention: one thread per position (threads 0..63)
    if (tid < MT) {
        const float* row = St + tid*RS;   // [h*96 + {q:0..31, k:32..63, v:64..95}]
        float s[16];
        #pragma unroll
        for (int i = 0; i < 16; i++) s[i] = 0.f;

        #pragma unroll
        for (int d4 = 0; d4 < 8; d4++) {
            float4 q4[4], k4[4];
            #pragma unroll
            for (int h = 0; h < 4; h++) {
                q4[h] = *(const float4*)&row[h*96      + d4*4];
                k4[h] = *(const float4*)&row[h*96 + 32 + d4*4];
            }
            #pragma unroll
            for (int h1 = 0; h1 < 4; h1++)
                #pragma unroll
                for (int h2 = 0; h2 < 4; h2++) {
                    float v = s[h1*4 + h2];
                    v = fmaf(q4[h1].x, k4[h2].x, v);
                    v = fmaf(q4[h1].y, k4[h2].y, v);
                    v = fmaf(q4[h1].z, k4[h2].z, v);
                    v = fmaf(q4[h1].w, k4[h2].w, v);
                    s[h1*4 + h2] = v;
                }
        }

        const float scale = 0.17677669529663687f;  // 32^-0.5
        float w[16];
        #pragma unroll
        for (int h1 = 0; h1 < 4; h1++) {
            float t0 = s[h1*4+0]*scale, t1 = s[h1*4+1]*scale;
            float t2 = s[h1*4+2]*scale, t3 = s[h1*4+3]*scale;
            float m  = fmaxf(fmaxf(t0, t1), fmaxf(t2, t3));
            float e0 = __expf(t0 - m), e1 = __expf(t1 - m);
            float e2 = __expf(t2 - m), e3 = __expf(t3 - m);
            float inv = 1.f / (e0 + e1 + e2 + e3);
            w[h1*4+0] = e0*inv; w[h1*4+1] = e1*inv;
            w[h1*4+2] = e2*inv; w[h1*4+3] = e3*inv;
        }

        float* outp = g_attn + (size_t)(mbase + tid) * DM;
        #pragma unroll
        for (int d4 = 0; d4 < 8; d4++) {
            float4 o[4];
            #pragma unroll
            for (int h1 = 0; h1 < 4; h1++) { o[h1].x = o[h1].y = o[h1].z = o[h1].w = 0.f; }
            #pragma unroll
            for (int h2 = 0; h2 < 4; h2++) {
                float4 v4 = *(const float4*)&row[h2*96 + 64 + d4*4];
                #pragma unroll
                for (int h1 = 0; h1 < 4; h1++) {
                    float a = w[h1*4 + h2];
                    o[h1].x = fmaf(a, v4.x, o[h1].x);
                    o[h1].y = fmaf(a, v4.y, o[h1].y);
                    o[h1].z = fmaf(a, v4.z, o[h1].z);
                    o[h1].w = fmaf(a, v4.w, o[h1].w);
                }
            }
            #pragma unroll
            for (int h1 = 0; h1 < 4; h1++)
                *(float4*)&outp[h1*32 + d4*4] = o[h1];
        }
    }
}

// ---------------------------------------------------------------------------
// Kernel 2: split-K partials of  C[b] = A2[b](128x8192) @ W_out(8192x128)
//   A2[b][i][j] = g_attn[b*S*D + i*S + j]  (free reshape)
// ---------------------------------------------------------------------------
__global__ __launch_bounds__(256)
void k2_partial(const float* __restrict__ Wout)
{
    __shared__ float As2[2][KC*129];   // [kk][row], +1 pad
    __shared__ float Bs2[2][KC*DM];    // [kk][col]

    const int tid = threadIdx.x;
    const int kc  = blockIdx.x;        // 0..15
    const int b   = blockIdx.y;        // 0..7
    const float* Ab = g_attn + (size_t)b * S_LEN * DM;
    const int kb0 = kc * KCH;

    float4 pa[2], pb[2];

    auto loadc = [&](int c) {
        #pragma unroll
        for (int t = 0; t < 2; t++) {
            int f   = tid + 256*t;
            int row = f >> 2, k4 = f & 3;
            pa[t] = *(const float4*)&Ab[(size_t)row * S_LEN + kb0 + c*KC + k4*4];
            int kk = f >> 5, d4 = f & 31;
            pb[t] = *(const float4*)&Wout[(size_t)(kb0 + c*KC + kk) * DM + d4*4];
        }
    };
    auto storec = [&](int buf) {
        #pragma unroll
        for (int t = 0; t < 2; t++) {
            int f   = tid + 256*t;
            int row = f >> 2, k4 = f & 3;
            As2[buf][(k4*4+0)*129 + row] = pa[t].x;
            As2[buf][(k4*4+1)*129 + row] = pa[t].y;
            As2[buf][(k4*4+2)*129 + row] = pa[t].z;
            As2[buf][(k4*4+3)*129 + row] = pa[t].w;
            int kk = f >> 5, d4 = f & 31;
            *(float4*)&Bs2[buf][kk*DM + d4*4] = pb[t];
        }
    };

    float acc[8][8];
    #pragma unroll
    for (int i = 0; i < 8; i++)
        #pragma unroll
        for (int j = 0; j < 8; j++) acc[i][j] = 0.f;

    const int tc = tid & 15, tr = tid >> 4;

    loadc(0); storec(0); __syncthreads();

    for (int c = 0; c < KCH/KC; c++) {           // 32 iterations
        if (c + 1 < KCH/KC) loadc(c + 1);
        const int buf = c & 1;
        #pragma unroll 4
        for (int kk = 0; kk < KC; kk++) {
            float a[8], bb[8];
            #pragma unroll
            for (int i = 0; i < 8; i++) a[i]  = As2[buf][kk*129 + tr + 16*i];
            #pragma unroll
            for (int j = 0; j < 8; j++) bb[j] = Bs2[buf][kk*DM  + tc + 16*j];
            #pragma unroll
            for (int i = 0; i < 8; i++)
                #pragma unroll
                for (int j = 0; j < 8; j++)
                    acc[i][j] = fmaf(a[i], bb[j], acc[i][j]);
        }
        __syncthreads();
        if (c + 1 < KCH/KC) { storec(buf ^ 1); __syncthreads(); }
    }

    float* pp = g_part + (size_t)(b*NKC + kc) * DM * DM;
    #pragma unroll
    for (int i = 0; i < 8; i++)
        #pragma unroll
        for (int j = 0; j < 8; j++)
            pp[(tr + 16*i)*DM + tc + 16*j] = acc[i][j];
}

// ---------------------------------------------------------------------------
// Kernel 3: reduce partials + bias
// ---------------------------------------------------------------------------
__global__ void k3_reduce(const float* __restrict__ bout, float* __restrict__ out)
{
    const int i  = blockIdx.x * 256 + threadIdx.x;   // 0..131071
    const int b  = i >> 14;
    const int rc = i & 16383;
    float s = bout[i & 127];
    const float* p = g_part + (size_t)b * NKC * DM * DM + rc;
    #pragma unroll
    for (int kc = 0; kc < NKC; kc++) s += p[kc * DM * DM];
    out[i] = s;
}

// ---------------------------------------------------------------------------
extern "C" void kernel_launch(void* const* d_in, const int* in_sizes, int n_in,
                              void* d_out, int out_size)
{
    const float* x    = (const float*)d_in[0];
    const float* Wqkv = (const float*)d_in[1];
    const float* bqkv = (const float*)d_in[2];
    const float* Wout = (const float*)d_in[3];
    const float* bout = (const float*)d_in[4];
    float* out = (float*)d_out;

    cudaFuncSetAttribute(k1_qkv_attn,
                         cudaFuncAttributeMaxDynamicSharedMemorySize, K1_SMEM_BYTES);

    k1_qkv_attn<<<(BATCH * S_LEN) / MT, TH1, K1_SMEM_BYTES>>>(x, Wqkv, bqkv);

    dim3 g2(NKC, BATCH);
    k2_partial<<<g2, 256>>>(Wout);

    k3_reduce<<<(BATCH * DM * DM) / 256, 256>>>(bout, out);
}

// round 2
// speedup vs baseline: 1.1177x; 1.1177x over previous
#include <cuda_runtime.h>

// Problem constants
#define S_LEN 8192
#define BATCH 8
#define DM    128            // d_model == K of QKV GEMM
#define NQKV  384            // 3*H*HD
#define MT    64             // positions per block (kernel 1)
#define TH1   512
#define RS    388            // staging row stride (floats)
#define K1_SMEM_FLOATS (MT*DM + DM*NQKV)     // 57344
#define K1_SMEM_BYTES  (K1_SMEM_FLOATS*4)    // 229376 B

#define KC    16             // k sub-chunk (kernel 2)
#define NKC   16             // number of split-K chunks
#define KCH   (S_LEN/NKC)    // 512 k per block

typedef unsigned long long u64;

// Packed fp32x2 helpers (sm_100+): exact fp32 FMA, 2x FP32-pipe width
__device__ __forceinline__ u64 pack2(float v) {
    u64 d; asm("mov.b64 %0, {%1, %1};" : "=l"(d) : "f"(v)); return d;
}
__device__ __forceinline__ void ffma2(u64& acc, u64 a, u64 b) {
    asm("fma.rn.f32x2 %0, %1, %2, %0;" : "+l"(acc) : "l"(a), "l"(b));
}
__device__ __forceinline__ u64 fadd2(u64 a, u64 b) {
    u64 d; asm("add.rn.f32x2 %0, %1, %2;" : "=l"(d) : "l"(a), "l"(b)); return d;
}

// Scratch (device globals: allowed; no cudaMalloc anywhere)
__device__ float g_attn[BATCH * S_LEN * DM];          // 33.5 MB attn out, flat (B,S,H,hd)
__device__ float g_part[NKC * BATCH * DM * DM];       // 8 MB split-K partials

// ---------------------------------------------------------------------------
// Kernel 1: qkv = x @ W_qkv + b ; per-position HxH attention ; write flat out
// ---------------------------------------------------------------------------
__global__ __launch_bounds__(TH1, 1)
void k1_qkv_attn(const float* __restrict__ x,
                 const float* __restrict__ Wqkv,
                 const float* __restrict__ bqkv)
{
    extern __shared__ float sm[];
    float* As = sm;             // [MT][DM]      32 KB
    float* Bs = sm + MT*DM;     // [DM][NQKV]   192 KB
    float* St = sm + MT*DM;     // staging [MT][RS] aliases Bs after GEMM

    const int tid   = threadIdx.x;
    const int mbase = blockIdx.x * MT;   // global row (b*S+s) base

    // Cooperative loads (coalesced float4)
    {
        const float4* xg = (const float4*)(x + (size_t)mbase * DM);
        float4* a4 = (float4*)As;
        #pragma unroll
        for (int t = 0; t < (MT*DM/4)/TH1; t++)       // 4
            a4[tid + TH1*t] = xg[tid + TH1*t];
        const float4* wg = (const float4*)Wqkv;
        float4* b4 = (float4*)Bs;
        #pragma unroll
        for (int t = 0; t < (DM*NQKV/4)/TH1; t++)     // 24
            b4[tid + TH1*t] = wg[tid + TH1*t];
    }
    __syncthreads();

    const int tcol = tid & 63;     // column-pair group: cols 2*tcol+128*j+{0,1}
    const int trow = tid >> 6;     // row group (warp-uniform -> broadcast A reads)

    // bias pairs (cols even -> 8B aligned)
    u64 bq[3];
    #pragma unroll
    for (int j = 0; j < 3; j++) bq[j] = *(const u64*)&bqkv[2*tcol + 128*j];

    u64 acc[8][3];
    #pragma unroll
    for (int i = 0; i < 8; i++)
        #pragma unroll
        for (int j = 0; j < 3; j++) acc[i][j] = 0ull;

    #pragma unroll 2
    for (int k0 = 0; k0 < DM; k0 += 4) {
        float4 a4[8];
        #pragma unroll
        for (int i = 0; i < 8; i++)
            a4[i] = *(const float4*)&As[(trow + 8*i)*DM + k0];
        #pragma unroll
        for (int kk = 0; kk < 4; kk++) {
            u64 bb[3];
            #pragma unroll
            for (int j = 0; j < 3; j++)
                bb[j] = *(const u64*)&Bs[(k0 + kk)*NQKV + 2*tcol + 128*j];
            #pragma unroll
            for (int i = 0; i < 8; i++) {
                float av = (kk == 0) ? a4[i].x : (kk == 1) ? a4[i].y
                         : (kk == 2) ? a4[i].z : a4[i].w;
                u64 ap = pack2(av);
                #pragma unroll
                for (int j = 0; j < 3; j++)
                    ffma2(acc[i][j], ap, bb[j]);
            }
        }
    }

    __syncthreads();   // everyone done reading Bs before staging overwrites it
    #pragma unroll
    for (int i = 0; i < 8; i++)
        #pragma unroll
        for (int j = 0; j < 3; j++)
            *(u64*)&St[(trow + 8*i)*RS + 2*tcol + 128*j] = fadd2(acc[i][j], bq[j]);
    __syncthreads();

    // Attention: one thread per position (threads 0..63)
    if (tid < MT) {
        const float* row = St + tid*RS;   // [h*96 + {q:0..31, k:32..63, v:64..95}]
        float s[16];
        #pragma unroll
        for (int i = 0; i < 16; i++) s[i] = 0.f;

        #pragma unroll
        for (int d4 = 0; d4 < 8; d4++) {
            float4 q4[4], k4[4];
            #pragma unroll
            for (int h = 0; h < 4; h++) {
                q4[h] = *(const float4*)&row[h*96      + d4*4];
                k4[h] = *(const float4*)&row[h*96 + 32 + d4*4];
            }
            #pragma unroll
            for (int h1 = 0; h1 < 4; h1++)
                #pragma unroll
                for (int h2 = 0; h2 < 4; h2++) {
                    float v = s[h1*4 + h2];
                    v = fmaf(q4[h1].x, k4[h2].x, v);
                    v = fmaf(q4[h1].y, k4[h2].y, v);
                    v = fmaf(q4[h1].z, k4[h2].z, v);
                    v = fmaf(q4[h1].w, k4[h2].w, v);
                    s[h1*4 + h2] = v;
                }
        }

        const float scale = 0.17677669529663687f;  // 32^-0.5
        float w[16];
        #pragma unroll
        for (int h1 = 0; h1 < 4; h1++) {
            float t0 = s[h1*4+0]*scale, t1 = s[h1*4+1]*scale;
            float t2 = s[h1*4+2]*scale, t3 = s[h1*4+3]*scale;
            float m  = fmaxf(fmaxf(t0, t1), fmaxf(t2, t3));
            float e0 = __expf(t0 - m), e1 = __expf(t1 - m);
            float e2 = __expf(t2 - m), e3 = __expf(t3 - m);
            float inv = 1.f / (e0 + e1 + e2 + e3);
            w[h1*4+0] = e0*inv; w[h1*4+1] = e1*inv;
            w[h1*4+2] = e2*inv; w[h1*4+3] = e3*inv;
        }

        float* outp = g_attn + (size_t)(mbase + tid) * DM;
        #pragma unroll
        for (int d4 = 0; d4 < 8; d4++) {
            float4 o[4];
            #pragma unroll
            for (int h1 = 0; h1 < 4; h1++) { o[h1].x = o[h1].y = o[h1].z = o[h1].w = 0.f; }
            #pragma unroll
            for (int h2 = 0; h2 < 4; h2++) {
                float4 v4 = *(const float4*)&row[h2*96 + 64 + d4*4];
                #pragma unroll
                for (int h1 = 0; h1 < 4; h1++) {
                    float a = w[h1*4 + h2];
                    o[h1].x = fmaf(a, v4.x, o[h1].x);
                    o[h1].y = fmaf(a, v4.y, o[h1].y);
                    o[h1].z = fmaf(a, v4.z, o[h1].z);
                    o[h1].w = fmaf(a, v4.w, o[h1].w);
                }
            }
            #pragma unroll
            for (int h1 = 0; h1 < 4; h1++)
                *(float4*)&outp[h1*32 + d4*4] = o[h1];
        }
    }
}

// ---------------------------------------------------------------------------
// Kernel 2: split-K partials of  C[b] = A2[b](128x8192) @ W_out(8192x128)
//   A2[b][i][j] = g_attn[b*S*D + i*S + j]  (free reshape)
// ---------------------------------------------------------------------------
__global__ __launch_bounds__(256)
void k2_partial(const float* __restrict__ Wout)
{
    __shared__ float As2[2][KC*129];   // [kk][row], +1 pad
    __shared__ float Bs2[2][KC*DM];    // [kk][col]

    const int tid = threadIdx.x;
    const int kc  = blockIdx.x;        // 0..15
    const int b   = blockIdx.y;        // 0..7
    const float* Ab = g_attn + (size_t)b * S_LEN * DM;
    const int kb0 = kc * KCH;

    float4 pa[2], pb[2];

    auto loadc = [&](int c) {
        #pragma unroll
        for (int t = 0; t < 2; t++) {
            int f   = tid + 256*t;
            int row = f >> 2, k4 = f & 3;
            pa[t] = *(const float4*)&Ab[(size_t)row * S_LEN + kb0 + c*KC + k4*4];
            int kk = f >> 5, d4 = f & 31;
            pb[t] = *(const float4*)&Wout[(size_t)(kb0 + c*KC + kk) * DM + d4*4];
        }
    };
    auto storec = [&](int buf) {
        #pragma unroll
        for (int t = 0; t < 2; t++) {
            int f   = tid + 256*t;
            int row = f >> 2, k4 = f & 3;
            As2[buf][(k4*4+0)*129 + row] = pa[t].x;
            As2[buf][(k4*4+1)*129 + row] = pa[t].y;
            As2[buf][(k4*4+2)*129 + row] = pa[t].z;
            As2[buf][(k4*4+3)*129 + row] = pa[t].w;
            int kk = f >> 5, d4 = f & 31;
            *(float4*)&Bs2[buf][kk*DM + d4*4] = pb[t];
        }
    };

    u64 acc[8][4];
    #pragma unroll
    for (int i = 0; i < 8; i++)
        #pragma unroll
        for (int j = 0; j < 4; j++) acc[i][j] = 0ull;

    const int tc = tid & 15, tr = tid >> 4;   // cols: 2*tc + 32*j + {0,1}

    loadc(0); storec(0); __syncthreads();

    for (int c = 0; c < KCH/KC; c++) {           // 32 iterations
        if (c + 1 < KCH/KC) loadc(c + 1);
        const int buf = c & 1;
        #pragma unroll 4
        for (int kk = 0; kk < KC; kk++) {
            u64 bb[4];
            #pragma unroll
            for (int j = 0; j < 4; j++)
                bb[j] = *(const u64*)&Bs2[buf][kk*DM + 2*tc + 32*j];
            #pragma unroll
            for (int i = 0; i < 8; i++) {
                u64 ap = pack2(As2[buf][kk*129 + tr + 16*i]);
                #pragma unroll
                for (int j = 0; j < 4; j++)
                    ffma2(acc[i][j], ap, bb[j]);
            }
        }
        __syncthreads();
        if (c + 1 < KCH/KC) { storec(buf ^ 1); __syncthreads(); }
    }

    float* pp = g_part + (size_t)(b*NKC + kc) * DM * DM;
    #pragma unroll
    for (int i = 0; i < 8; i++)
        #pragma unroll
        for (int j = 0; j < 4; j++)
            *(u64*)&pp[(tr + 16*i)*DM + 2*tc + 32*j] = acc[i][j];
}

// ---------------------------------------------------------------------------
// Kernel 3: reduce partials + bias
// ---------------------------------------------------------------------------
__global__ void k3_reduce(const float* __restrict__ bout, float* __restrict__ out)
{
    const int i  = blockIdx.x * 256 + threadIdx.x;   // 0..131071
    const int b  = i >> 14;
    const int rc = i & 16383;
    float s = bout[i & 127];
    const float* p = g_part + (size_t)b * NKC * DM * DM + rc;
    #pragma unroll
    for (int kc = 0; kc < NKC; kc++) s += p[kc * DM * DM];
    out[i] = s;
}

// ---------------------------------------------------------------------------
extern "C" void kernel_launch(void* const* d_in, const int* in_sizes, int n_in,
                              void* d_out, int out_size)
{
    const float* x    = (const float*)d_in[0];
    const float* Wqkv = (const float*)d_in[1];
    const float* bqkv = (const float*)d_in[2];
    const float* Wout = (const float*)d_in[3];
    const float* bout = (const float*)d_in[4];
    float* out = (float*)d_out;

    cudaFuncSetAttribute(k1_qkv_attn,
                         cudaFuncAttributeMaxDynamicSharedMemorySize, K1_SMEM_BYTES);

    k1_qkv_attn<<<(BATCH * S_LEN) / MT, TH1, K1_SMEM_BYTES>>>(x, Wqkv, bqkv);

    dim3 g2(NKC, BATCH);
    k2_partial<<<g2, 256>>>(Wout);

    k3_reduce<<<(BATCH * DM * DM) / 256, 256>>>(bout, out);
}

// round 5
// speedup vs baseline: 2.0046x; 1.7935x over previous
#include <cuda_runtime.h>
#include <cuda_bf16.h>

typedef unsigned int u32;

// Problem constants
#define S_LEN 8192
#define BATCH 8
#define DM    128
#define NQKV  384
#define MT1   64             // rows per k1 block
#define NKC   16
#define KCH   (S_LEN/NKC)    // 512

// ---- scratch (device globals; no cudaMalloc anywhere) ----
__device__ float g_attn[BATCH * S_LEN * DM];                 // 33.5 MB
__device__ float g_part[NKC * BATCH * DM * DM];              // 8 MB
__device__ __align__(16) __nv_bfloat16 g_wh[DM * NQKV];      // W_qkv hi  [k][n]
__device__ __align__(16) __nv_bfloat16 g_wl[DM * NQKV];      // W_qkv lo  [k][n]

// ---- k1 smem layout (bytes) ----
#define SM_BIAS 0                         // 384 f32
#define SM_AH   1536                      // [64][136] bf16 = 17408
#define SM_AL   (SM_AH + 17408)
#define SM_BH   (SM_AL + 17408)           // [128][136] bf16 = 34816
#define SM_BL   (SM_BH + 34816)
#define SM_ST   (SM_BL + 34816)           // [64][392] f32 = 100352
#define SM_TOT  (SM_ST + 100352)          // 206336

// ---- k2 smem layout (bytes) ----
#define K2_AH   0                         // [2][128*40] bf16 = 2*10240
#define K2_AL   20480
#define K2_BH   40960                     // [2][32*136] bf16 = 2*8704
#define K2_BL   58368
#define K2_TOT  75776

// ---------------------------------------------------------------------------
__device__ __forceinline__ u32 smem_u32(const void* p) {
    u32 a;
    asm("{ .reg .u64 t; cvta.to.shared.u64 t, %1; cvt.u32.u64 %0, t; }" : "=r"(a) : "l"(p));
    return a;
}
__device__ __forceinline__ void ldsm4(u32* r, u32 a) {
    asm volatile("ldmatrix.sync.aligned.m8n8.x4.shared.b16 {%0,%1,%2,%3}, [%4];"
        : "=r"(r[0]), "=r"(r[1]), "=r"(r[2]), "=r"(r[3]) : "r"(a));
}
__device__ __forceinline__ void ldsm4t(u32* r, u32 a) {
    asm volatile("ldmatrix.sync.aligned.m8n8.x4.trans.shared.b16 {%0,%1,%2,%3}, [%4];"
        : "=r"(r[0]), "=r"(r[1]), "=r"(r[2]), "=r"(r[3]) : "r"(a));
}
__device__ __forceinline__ void mma16816(float* d, const u32* a, const u32* b) {
    asm volatile(
        "mma.sync.aligned.m16n8k16.row.col.f32.bf16.bf16.f32 "
        "{%0,%1,%2,%3}, {%4,%5,%6,%7}, {%8,%9}, {%0,%1,%2,%3};"
        : "+f"(d[0]), "+f"(d[1]), "+f"(d[2]), "+f"(d[3])
        : "r"(a[0]), "r"(a[1]), "r"(a[2]), "r"(a[3]), "r"(b[0]), "r"(b[1]));
}
// fp32 -> bf16 hi/lo pair conversion (4 lanes)
__device__ __forceinline__ void cvt_hl4(float4 v, uint2& h, uint2& l) {
    __nv_bfloat16 h0 = __float2bfloat16(v.x), h1 = __float2bfloat16(v.y);
    __nv_bfloat16 h2 = __float2bfloat16(v.z), h3 = __float2bfloat16(v.w);
    __nv_bfloat16 l0 = __float2bfloat16(v.x - __bfloat162float(h0));
    __nv_bfloat16 l1 = __float2bfloat16(v.y - __bfloat162float(h1));
    __nv_bfloat16 l2 = __float2bfloat16(v.z - __bfloat162float(h2));
    __nv_bfloat16 l3 = __float2bfloat16(v.w - __bfloat162float(h3));
    h.x = (u32)__bfloat16_as_ushort(h0) | ((u32)__bfloat16_as_ushort(h1) << 16);
    h.y = (u32)__bfloat16_as_ushort(h2) | ((u32)__bfloat16_as_ushort(h3) << 16);
    l.x = (u32)__bfloat16_as_ushort(l0) | ((u32)__bfloat16_as_ushort(l1) << 16);
    l.y = (u32)__bfloat16_as_ushort(l2) | ((u32)__bfloat16_as_ushort(l3) << 16);
}

// ---------------------------------------------------------------------------
// k0: convert W_qkv fp32 [128][384] -> bf16 hi/lo arrays (same layout)
// ---------------------------------------------------------------------------
__global__ void k0_convW(const float* __restrict__ W)
{
    int idx = blockIdx.x * 256 + threadIdx.x;
    if (idx >= DM * NQKV) return;
    float w = W[idx];
    __nv_bfloat16 h = __float2bfloat16(w);
    __nv_bfloat16 l = __float2bfloat16(w - __bfloat162float(h));
    g_wh[idx] = h;
    g_wl[idx] = l;
}

// ---------------------------------------------------------------------------
// k1: qkv = x @ W_qkv + b via bf16 hi/lo mma.sync; then per-position attention
// ---------------------------------------------------------------------------
__global__ __launch_bounds__(256, 1)
void k1_qkv_attn(const float* __restrict__ x, const float* __restrict__ bqkv)
{
    extern __shared__ char smem[];
    const u32 sb  = smem_u32(smem);
    const int tid = threadIdx.x;
    const int lane = tid & 31, wid = tid >> 5;
    const int mbase = blockIdx.x * MT1;

    float* sbias = (float*)(smem + SM_BIAS);
    for (int i = tid; i < NQKV; i += 256) sbias[i] = bqkv[i];

    // A tile: 64x128 fp32 -> bf16 hi/lo, pitch 136
    {
        const float4* xg = (const float4*)(x + (size_t)mbase * DM);
        #pragma unroll
        for (int t = 0; t < 8; t++) {
            int f = tid + 256 * t;              // 2048 float4
            int row = f >> 5, k0 = (f & 31) * 4;
            uint2 h, l;
            cvt_hl4(xg[f], h, l);
            *(uint2*)(smem + SM_AH + (row * 136 + k0) * 2) = h;
            *(uint2*)(smem + SM_AL + (row * 136 + k0) * 2) = l;
        }
    }
    // B tile for nt=0
    {
        const uint4* srh = (const uint4*)g_wh;
        const uint4* srl = (const uint4*)g_wl;
        #pragma unroll
        for (int t = 0; t < 8; t++) {
            int f = tid + 256 * t;              // 2048 uint4 (128 rows x 16)
            int row = f >> 4, c8 = (f & 15) * 8;
            // global [k][384] bf16: uint4 index = (row*384 + c8)/8
            *(uint4*)(smem + SM_BH + (row * 136 + c8) * 2) = srh[(row * 384 + c8) >> 3];
            *(uint4*)(smem + SM_BL + (row * 136 + c8) * 2) = srl[(row * 384 + c8) >> 3];
        }
    }
    __syncthreads();

    const int m0 = (wid >> 2) * 32;     // 2 M-groups of 32 rows
    const int n0 = (wid & 3) * 32;      // 4 N-groups of 32 cols
    const u32 arow = (u32)(lane & 15);
    const u32 csel = (u32)((lane >> 4) << 3);
    float* St = (float*)(smem + SM_ST);

    for (int nt = 0; nt < 3; nt++) {
        float acc[2][4][4];
        #pragma unroll
        for (int mf = 0; mf < 2; mf++)
            #pragma unroll
            for (int nf = 0; nf < 4; nf++)
                #pragma unroll
                for (int r = 0; r < 4; r++) acc[mf][nf][r] = 0.f;

        #pragma unroll
        for (int ks = 0; ks < 8; ks++) {
            const int k0 = ks * 16;
            u32 ah[2][4], al[2][4], bh[4][2], bl[4][2];
            #pragma unroll
            for (int mf = 0; mf < 2; mf++) {
                u32 off = ((m0 + mf * 16 + arow) * 136 + csel + k0) * 2;
                ldsm4(ah[mf], sb + SM_AH + off);
                ldsm4(al[mf], sb + SM_AL + off);
            }
            #pragma unroll
            for (int h2 = 0; h2 < 2; h2++) {
                u32 off = ((k0 + arow) * 136 + n0 + h2 * 16 + csel) * 2;
                u32 r[4];
                ldsm4t(r, sb + SM_BH + off);
                bh[h2*2][0] = r[0]; bh[h2*2][1] = r[1];
                bh[h2*2+1][0] = r[2]; bh[h2*2+1][1] = r[3];
                ldsm4t(r, sb + SM_BL + off);
                bl[h2*2][0] = r[0]; bl[h2*2][1] = r[1];
                bl[h2*2+1][0] = r[2]; bl[h2*2+1][1] = r[3];
            }
            #pragma unroll
            for (int mf = 0; mf < 2; mf++)
                #pragma unroll
                for (int nf = 0; nf < 4; nf++) {
                    mma16816(acc[mf][nf], ah[mf], bh[nf]);
                    mma16816(acc[mf][nf], ah[mf], bl[nf]);
                    mma16816(acc[mf][nf], al[mf], bh[nf]);
                }
        }

        // stage accum (+bias) to St
        {
            const int r0 = m0 + (lane >> 2);
            const int cb = nt * 128 + n0 + (lane & 3) * 2;
            #pragma unroll
            for (int mf = 0; mf < 2; mf++)
                #pragma unroll
                for (int nf = 0; nf < 4; nf++) {
                    int row = r0 + mf * 16, col = cb + nf * 8;
                    float2 b2 = *(float2*)&sbias[col];
                    *(float2*)&St[row * 392 + col] =
                        make_float2(acc[mf][nf][0] + b2.x, acc[mf][nf][1] + b2.y);
                    *(float2*)&St[(row + 8) * 392 + col] =
                        make_float2(acc[mf][nf][2] + b2.x, acc[mf][nf][3] + b2.y);
                }
        }

        if (nt < 2) {
            __syncthreads();    // all warps done reading B tile
            const uint4* srh = (const uint4*)g_wh;
            const uint4* srl = (const uint4*)g_wl;
            #pragma unroll
            for (int t = 0; t < 8; t++) {
                int f = tid + 256 * t;
                int row = f >> 4, c8 = (f & 15) * 8;
                int gcol = (nt + 1) * 128 + c8;
                *(uint4*)(smem + SM_BH + (row * 136 + c8) * 2) = srh[(row * 384 + gcol) >> 3];
                *(uint4*)(smem + SM_BL + (row * 136 + c8) * 2) = srl[(row * 384 + gcol) >> 3];
            }
            __syncthreads();
        }
    }
    __syncthreads();

    // Attention: one thread per position (threads 0..63)
    if (tid < MT1) {
        const float* row = St + tid * 392;   // [h*96 + {q:0..31, k:32..63, v:64..95}]
        float s[16];
        #pragma unroll
        for (int i = 0; i < 16; i++) s[i] = 0.f;

        #pragma unroll
        for (int d4 = 0; d4 < 8; d4++) {
            float4 q4[4], k4[4];
            #pragma unroll
            for (int h = 0; h < 4; h++) {
                q4[h] = *(const float4*)&row[h*96      + d4*4];
                k4[h] = *(const float4*)&row[h*96 + 32 + d4*4];
            }
            #pragma unroll
            for (int h1 = 0; h1 < 4; h1++)
                #pragma unroll
                for (int h2 = 0; h2 < 4; h2++) {
                    float v = s[h1*4 + h2];
                    v = fmaf(q4[h1].x, k4[h2].x, v);
                    v = fmaf(q4[h1].y, k4[h2].y, v);
                    v = fmaf(q4[h1].z, k4[h2].z, v);
                    v = fmaf(q4[h1].w, k4[h2].w, v);
                    s[h1*4 + h2] = v;
                }
        }

        const float scale = 0.17677669529663687f;  // 32^-0.5
        float w[16];
        #pragma unroll
        for (int h1 = 0; h1 < 4; h1++) {
            float t0 = s[h1*4+0]*scale, t1 = s[h1*4+1]*scale;
            float t2 = s[h1*4+2]*scale, t3 = s[h1*4+3]*scale;
            float m  = fmaxf(fmaxf(t0, t1), fmaxf(t2, t3));
            float e0 = __expf(t0 - m), e1 = __expf(t1 - m);
            float e2 = __expf(t2 - m), e3 = __expf(t3 - m);
            float inv = 1.f / (e0 + e1 + e2 + e3);
            w[h1*4+0] = e0*inv; w[h1*4+1] = e1*inv;
            w[h1*4+2] = e2*inv; w[h1*4+3] = e3*inv;
        }

        float* outp = g_attn + (size_t)(mbase + tid) * DM;
        #pragma unroll
        for (int d4 = 0; d4 < 8; d4++) {
            float4 o[4];
            #pragma unroll
            for (int h1 = 0; h1 < 4; h1++) { o[h1].x = o[h1].y = o[h1].z = o[h1].w = 0.f; }
            #pragma unroll
            for (int h2 = 0; h2 < 4; h2++) {
                float4 v4 = *(const float4*)&row[h2*96 + 64 + d4*4];
                #pragma unroll
                for (int h1 = 0; h1 < 4; h1++) {
                    float a = w[h1*4 + h2];
                    o[h1].x = fmaf(a, v4.x, o[h1].x);
                    o[h1].y = fmaf(a, v4.y, o[h1].y);
                    o[h1].z = fmaf(a, v4.z, o[h1].z);
                    o[h1].w = fmaf(a, v4.w, o[h1].w);
                }
            }
            #pragma unroll
            for (int h1 = 0; h1 < 4; h1++)
                *(float4*)&outp[h1*32 + d4*4] = o[h1];
        }
    }
}

// ---------------------------------------------------------------------------
// k2: split-K partials of C[b] = A2[b](128x8192) @ W_out(8192x128), bf16 hi/lo mma
//   A2[b][i][j] = g_attn[b*D*S + i*S + j]
// ---------------------------------------------------------------------------
__global__ __launch_bounds__(256, 1)
void k2_partial(const float* __restrict__ Wout)
{
    extern __shared__ char sm2[];
    const u32 sb = smem_u32(sm2);
    const int tid = threadIdx.x;
    const int lane = tid & 31, wid = tid >> 5;
    const int kc = blockIdx.x, b = blockIdx.y;
    const float* Ab = g_attn + (size_t)b * DM * S_LEN;
    const int kb0 = kc * KCH;

    const int m0 = (wid >> 2) * 64;     // 2 M-groups of 64 rows
    const int n0 = (wid & 3) * 32;      // 4 N-groups of 32 cols
    const u32 arow = (u32)(lane & 15);
    const u32 csel = (u32)((lane >> 4) << 3);

    float acc[4][4][4];
    #pragma unroll
    for (int mf = 0; mf < 4; mf++)
        #pragma unroll
        for (int nf = 0; nf < 4; nf++)
            #pragma unroll
            for (int r = 0; r < 4; r++) acc[mf][nf][r] = 0.f;

    float4 pa[4], pb[4];
    auto gload = [&](int c) {
        const int kpos = kb0 + c * 32;
        #pragma unroll
        for (int t = 0; t < 4; t++) {
            int f = tid + 256 * t;
            pa[t] = *(const float4*)&Ab[(size_t)(f >> 3) * S_LEN + kpos + (f & 7) * 4];
            pb[t] = *(const float4*)&Wout[(size_t)(kpos + (f >> 5)) * DM + (f & 31) * 4];
        }
    };
    auto sstore = [&](int buf) {
        #pragma unroll
        for (int t = 0; t < 4; t++) {
            int f = tid + 256 * t;
            uint2 h, l;
            cvt_hl4(pa[t], h, l);
            {
                int row = f >> 3, k = (f & 7) * 4;
                *(uint2*)(sm2 + K2_AH + buf * 10240 + (row * 40 + k) * 2) = h;
                *(uint2*)(sm2 + K2_AL + buf * 10240 + (row * 40 + k) * 2) = l;
            }
            cvt_hl4(pb[t], h, l);
            {
                int row = f >> 5, n = (f & 31) * 4;
                *(uint2*)(sm2 + K2_BH + buf * 8704 + (row * 136 + n) * 2) = h;
                *(uint2*)(sm2 + K2_BL + buf * 8704 + (row * 136 + n) * 2) = l;
            }
        }
    };

    gload(0); sstore(0); __syncthreads();

    int buf = 0;
    for (int c = 0; c < 16; c++) {
        if (c < 15) gload(c + 1);
        #pragma unroll
        for (int kk = 0; kk < 32; kk += 16) {
            u32 ah[4][4], al[4][4], bh[4][2], bl[4][2];
            #pragma unroll
            for (int h2 = 0; h2 < 2; h2++) {
                u32 off = ((kk + arow) * 136 + n0 + h2 * 16 + csel) * 2;
                u32 r[4];
                ldsm4t(r, sb + K2_BH + buf * 8704 + off);
                bh[h2*2][0] = r[0]; bh[h2*2][1] = r[1];
                bh[h2*2+1][0] = r[2]; bh[h2*2+1][1] = r[3];
                ldsm4t(r, sb + K2_BL + buf * 8704 + off);
                bl[h2*2][0] = r[0]; bl[h2*2][1] = r[1];
                bl[h2*2+1][0] = r[2]; bl[h2*2+1][1] = r[3];
            }
            #pragma unroll
            for (int mf = 0; mf < 4; mf++) {
                u32 off = ((m0 + mf * 16 + arow) * 40 + csel + kk) * 2;
                ldsm4(ah[mf], sb + K2_AH + buf * 10240 + off);
                ldsm4(al[mf], sb + K2_AL + buf * 10240 + off);
            }
            #pragma unroll
            for (int mf = 0; mf < 4; mf++)
                #pragma unroll
                for (int nf = 0; nf < 4; nf++) {
                    mma16816(acc[mf][nf], ah[mf], bh[nf]);
                    mma16816(acc[mf][nf], ah[mf], bl[nf]);
                    mma16816(acc[mf][nf], al[mf], bh[nf]);
                }
        }
        if (c < 15) sstore(buf ^ 1);
        __syncthreads();
        buf ^= 1;
    }

    float* pp = g_part + (size_t)(b * NKC + kc) * DM * DM;
    const int r0 = m0 + (lane >> 2);
    const int cb = n0 + (lane & 3) * 2;
    #pragma unroll
    for (int mf = 0; mf < 4; mf++)
        #pragma unroll
        for (int nf = 0; nf < 4; nf++) {
            int row = r0 + mf * 16, col = cb + nf * 8;
            *(float2*)&pp[row * DM + col] = make_float2(acc[mf][nf][0], acc[mf][nf][1]);
            *(float2*)&pp[(row + 8) * DM + col] = make_float2(acc[mf][nf][2], acc[mf][nf][3]);
        }
}

// ---------------------------------------------------------------------------
// k3: reduce partials + bias
// ---------------------------------------------------------------------------
__global__ void k3_reduce(const float* __restrict__ bout, float* __restrict__ out)
{
    const int i  = blockIdx.x * 256 + threadIdx.x;
    const int b  = i >> 14;
    const int rc = i & 16383;
    float s = bout[i & 127];
    const float* p = g_part + (size_t)b * NKC * DM * DM + rc;
    #pragma unroll
    for (int kc = 0; kc < NKC; kc++) s += p[kc * DM * DM];
    out[i] = s;
}

// ---------------------------------------------------------------------------
extern "C" void kernel_launch(void* const* d_in, const int* in_sizes, int n_in,
                              void* d_out, int out_size)
{
    const float* x    = (const float*)d_in[0];
    const float* Wqkv = (const float*)d_in[1];
    const float* bqkv = (const float*)d_in[2];
    const float* Wout = (const float*)d_in[3];
    const float* bout = (const float*)d_in[4];
    float* out = (float*)d_out;

    cudaFuncSetAttribute(k1_qkv_attn,
                         cudaFuncAttributeMaxDynamicSharedMemorySize, SM_TOT);
    cudaFuncSetAttribute(k2_partial,
                         cudaFuncAttributeMaxDynamicSharedMemorySize, K2_TOT);

    k0_convW<<<(DM * NQKV + 255) / 256, 256>>>(Wqkv);
    k1_qkv_attn<<<(BATCH * S_LEN) / MT1, 256, SM_TOT>>>(x, bqkv);

    dim3 g2(NKC, BATCH);
    k2_partial<<<g2, 256, K2_TOT>>>(Wout);

    k3_reduce<<<(BATCH * DM * DM) / 256, 256>>>(bout, out);
}

// round 6
// speedup vs baseline: 3.0046x; 1.4989x over previous
#include <cuda_runtime.h>
#include <cuda_fp16.h>

typedef unsigned int u32;

// Problem constants
#define S_LEN 8192
#define BATCH 8
#define DM    128
#define NQKV  384
#define MT1   64             // rows per k1 block
#define NKC   16
#define KCH   (S_LEN/NKC)    // 512

// ---- scratch (device globals; no cudaMalloc anywhere) ----
__device__ __align__(16) __half g_attn_h[BATCH * S_LEN * DM];   // 16.7 MB attn out (fp16)
__device__ float g_part[NKC * BATCH * DM * DM];                 // 8 MB split-K partials
__device__ __align__(16) __half g_wq[DM * NQKV];                // W_qkv fp16 [k][n]
__device__ __align__(16) __half g_wo[S_LEN * DM];               // W_out fp16 [k][n]

// ---- k1 smem layout (bytes) ----
#define SM_BIAS 0                         // 384 f32 = 1536
#define SM_A    1536                      // [64][136] fp16 = 17408
#define SM_B    (SM_A + 17408)            // [128][136] fp16 = 34816
#define SM_ST   (SM_B + 34816)            // [64][385] f32 = 98560
#define SM_TOT  (SM_ST + 98560)           // 152320
#define STP     385                       // St pitch (odd mod 32 -> conflict-free)

// ---------------------------------------------------------------------------
__device__ __forceinline__ u32 smem_u32(const void* p) {
    u32 a;
    asm("{ .reg .u64 t; cvta.to.shared.u64 t, %1; cvt.u32.u64 %0, t; }" : "=r"(a) : "l"(p));
    return a;
}
__device__ __forceinline__ void ldsm4(u32* r, u32 a) {
    asm volatile("ldmatrix.sync.aligned.m8n8.x4.shared.b16 {%0,%1,%2,%3}, [%4];"
        : "=r"(r[0]), "=r"(r[1]), "=r"(r[2]), "=r"(r[3]) : "r"(a));
}
__device__ __forceinline__ void ldsm4t(u32* r, u32 a) {
    asm volatile("ldmatrix.sync.aligned.m8n8.x4.trans.shared.b16 {%0,%1,%2,%3}, [%4];"
        : "=r"(r[0]), "=r"(r[1]), "=r"(r[2]), "=r"(r[3]) : "r"(a));
}
__device__ __forceinline__ void mma16816(float* d, const u32* a, const u32* b) {
    asm volatile(
        "mma.sync.aligned.m16n8k16.row.col.f32.f16.f16.f32 "
        "{%0,%1,%2,%3}, {%4,%5,%6,%7}, {%8,%9}, {%0,%1,%2,%3};"
        : "+f"(d[0]), "+f"(d[1]), "+f"(d[2]), "+f"(d[3])
        : "r"(a[0]), "r"(a[1]), "r"(a[2]), "r"(a[3]), "r"(b[0]), "r"(b[1]));
}
__device__ __forceinline__ uint2 cvt_h4(float4 v) {
    __half2 a = __floats2half2_rn(v.x, v.y);
    __half2 b = __floats2half2_rn(v.z, v.w);
    uint2 r;
    r.x = *(u32*)&a;
    r.y = *(u32*)&b;
    return r;
}

// ---------------------------------------------------------------------------
// k0a/k0b: one-time fp32 -> fp16 weight conversions
// ---------------------------------------------------------------------------
__global__ void k0a_convWq(const float* __restrict__ W)
{
    int idx = blockIdx.x * 256 + threadIdx.x;
    if (idx < DM * NQKV) g_wq[idx] = __float2half_rn(W[idx]);
}
__global__ void k0b_convWo(const float* __restrict__ W)
{
    int idx = blockIdx.x * 256 + threadIdx.x;   // grid covers 1048576
    float4 v = *(const float4*)&W[idx * 4];
    *(uint2*)&g_wo[idx * 4] = cvt_h4(v);
}

// ---------------------------------------------------------------------------
// k1: qkv = x @ W_qkv + b via fp16 mma.sync; per-position HxH attention;
//     writes attention output as fp16 to g_attn_h
// ---------------------------------------------------------------------------
__global__ __launch_bounds__(256, 1)
void k1_qkv_attn(const float* __restrict__ x, const float* __restrict__ bqkv)
{
    extern __shared__ char smem[];
    const u32 sb  = smem_u32(smem);
    const int tid = threadIdx.x;
    const int lane = tid & 31, wid = tid >> 5;
    const int mbase = blockIdx.x * MT1;

    float* sbias = (float*)(smem + SM_BIAS);
    for (int i = tid; i < NQKV; i += 256) sbias[i] = bqkv[i];

    // A tile: 64x128 fp32 -> fp16, pitch 136
    {
        const float4* xg = (const float4*)(x + (size_t)mbase * DM);
        #pragma unroll
        for (int t = 0; t < 8; t++) {
            int f = tid + 256 * t;              // 2048 float4
            int row = f >> 5, k0 = (f & 31) * 4;
            *(uint2*)(smem + SM_A + (row * 136 + k0) * 2) = cvt_h4(xg[f]);
        }
    }
    // B tile nt=0: copy fp16 W columns [0,128)
    {
        const uint4* src = (const uint4*)g_wq;   // rows of 48 uint4 (384 fp16)
        #pragma unroll
        for (int t = 0; t < 8; t++) {
            int f = tid + 256 * t;               // 2048 uint4
            int row = f >> 4, c8 = (f & 15);
            *(uint4*)(smem + SM_B + (row * 136 + c8 * 8) * 2) = src[row * 48 + c8];
        }
    }
    __syncthreads();

    const int m0 = (wid >> 2) * 32;     // 2 M-groups of 32 rows
    const int n0 = (wid & 3) * 32;      // 4 N-groups of 32 cols
    const u32 arow = (u32)(lane & 15);
    const u32 csel = (u32)((lane >> 4) << 3);
    float* St = (float*)(smem + SM_ST);

    for (int nt = 0; nt < 3; nt++) {
        // prefetch next B tile into registers (hidden under MMA)
        uint4 pb[8];
        if (nt < 2) {
            const uint4* src = (const uint4*)g_wq;
            const int gc8 = (nt + 1) * 16;
            #pragma unroll
            for (int t = 0; t < 8; t++) {
                int f = tid + 256 * t;
                int row = f >> 4, c8 = (f & 15);
                pb[t] = src[row * 48 + gc8 + c8];
            }
        }

        float acc[2][4][4];
        #pragma unroll
        for (int mf = 0; mf < 2; mf++)
            #pragma unroll
            for (int nf = 0; nf < 4; nf++)
                #pragma unroll
                for (int r = 0; r < 4; r++) acc[mf][nf][r] = 0.f;

        #pragma unroll
        for (int ks = 0; ks < 8; ks++) {
            const int k0 = ks * 16;
            u32 a[2][4], bfr[4][2];
            #pragma unroll
            for (int mf = 0; mf < 2; mf++)
                ldsm4(a[mf], sb + SM_A + ((m0 + mf * 16 + arow) * 136 + csel + k0) * 2);
            #pragma unroll
            for (int h2 = 0; h2 < 2; h2++) {
                u32 r[4];
                ldsm4t(r, sb + SM_B + ((k0 + arow) * 136 + n0 + h2 * 16 + csel) * 2);
                bfr[h2*2][0] = r[0];   bfr[h2*2][1] = r[1];
                bfr[h2*2+1][0] = r[2]; bfr[h2*2+1][1] = r[3];
            }
            #pragma unroll
            for (int mf = 0; mf < 2; mf++)
                #pragma unroll
                for (int nf = 0; nf < 4; nf++)
                    mma16816(acc[mf][nf], a[mf], bfr[nf]);
        }

        // stage accum (+bias) to St (pitch 385, scalar stores)
        {
            const int r0 = m0 + (lane >> 2);
            const int cb = nt * 128 + n0 + (lane & 3) * 2;
            #pragma unroll
            for (int mf = 0; mf < 2; mf++)
                #pragma unroll
                for (int nf = 0; nf < 4; nf++) {
                    int row = r0 + mf * 16, col = cb + nf * 8;
                    St[row * STP + col]       = acc[mf][nf][0] + sbias[col];
                    St[row * STP + col + 1]   = acc[mf][nf][1] + sbias[col + 1];
                    St[(row+8) * STP + col]   = acc[mf][nf][2] + sbias[col];
                    St[(row+8) * STP + col+1] = acc[mf][nf][3] + sbias[col + 1];
                }
        }

        if (nt < 2) {
            __syncthreads();    // all warps done reading current B tile
            #pragma unroll
            for (int t = 0; t < 8; t++) {
                int f = tid + 256 * t;
                int row = f >> 4, c8 = (f & 15);
                *(uint4*)(smem + SM_B + (row * 136 + c8 * 8) * 2) = pb[t];
            }
            __syncthreads();
        }
    }
    __syncthreads();

    // Attention: one thread per position (threads 0..63); pitch-385 -> bank-clean
    if (tid < MT1) {
        const float* row = St + tid * STP;   // [h*96 + {q:0..31, k:32..63, v:64..95}]
        float s[16];
        #pragma unroll
        for (int i = 0; i < 16; i++) s[i] = 0.f;

        #pragma unroll
        for (int d4 = 0; d4 < 8; d4++) {
            float q4[4][4], k4[4][4];
            #pragma unroll
            for (int h = 0; h < 4; h++)
                #pragma unroll
                for (int e = 0; e < 4; e++) {
                    q4[h][e] = row[h*96      + d4*4 + e];
                    k4[h][e] = row[h*96 + 32 + d4*4 + e];
                }
            #pragma unroll
            for (int h1 = 0; h1 < 4; h1++)
                #pragma unroll
                for (int h2 = 0; h2 < 4; h2++) {
                    float v = s[h1*4 + h2];
                    #pragma unroll
                    for (int e = 0; e < 4; e++) v = fmaf(q4[h1][e], k4[h2][e], v);
                    s[h1*4 + h2] = v;
                }
        }

        const float scale = 0.17677669529663687f;  // 32^-0.5
        float w[16];
        #pragma unroll
        for (int h1 = 0; h1 < 4; h1++) {
            float t0 = s[h1*4+0]*scale, t1 = s[h1*4+1]*scale;
            float t2 = s[h1*4+2]*scale, t3 = s[h1*4+3]*scale;
            float m  = fmaxf(fmaxf(t0, t1), fmaxf(t2, t3));
            float e0 = __expf(t0 - m), e1 = __expf(t1 - m);
            float e2 = __expf(t2 - m), e3 = __expf(t3 - m);
            float inv = 1.f / (e0 + e1 + e2 + e3);
            w[h1*4+0] = e0*inv; w[h1*4+1] = e1*inv;
            w[h1*4+2] = e2*inv; w[h1*4+3] = e3*inv;
        }

        __half* outp = g_attn_h + (size_t)(mbase + tid) * DM;
        #pragma unroll
        for (int d4 = 0; d4 < 8; d4++) {
            float o[4][4];
            #pragma unroll
            for (int h1 = 0; h1 < 4; h1++)
                #pragma unroll
                for (int e = 0; e < 4; e++) o[h1][e] = 0.f;
            #pragma unroll
            for (int h2 = 0; h2 < 4; h2++) {
                float v4[4];
                #pragma unroll
                for (int e = 0; e < 4; e++) v4[e] = row[h2*96 + 64 + d4*4 + e];
                #pragma unroll
                for (int h1 = 0; h1 < 4; h1++) {
                    float a = w[h1*4 + h2];
                    #pragma unroll
                    for (int e = 0; e < 4; e++) o[h1][e] = fmaf(a, v4[e], o[h1][e]);
                }
            }
            #pragma unroll
            for (int h1 = 0; h1 < 4; h1++) {
                float4 of = make_float4(o[h1][0], o[h1][1], o[h1][2], o[h1][3]);
                *(uint2*)&outp[h1*32 + d4*4] = cvt_h4(of);
            }
        }
    }
}

// ---------------------------------------------------------------------------
// k2: split-K partials of C[b] = A2[b](128x8192) @ W_out(8192x128), fp16 mma
//   A2[b][i][j] = g_attn_h[b*D*S + i*S + j]
// ---------------------------------------------------------------------------
__global__ __launch_bounds__(256, 1)
void k2_partial()
{
    __shared__ __align__(16) __half As2[2][128 * 40];   // pitch 40
    __shared__ __align__(16) __half Bs2[2][32 * 136];   // pitch 136
    const u32 sa = smem_u32(As2);
    const u32 sbm = smem_u32(Bs2);

    const int tid = threadIdx.x;
    const int lane = tid & 31, wid = tid >> 5;
    const int kc = blockIdx.x, b = blockIdx.y;
    const __half* Ab = g_attn_h + (size_t)b * DM * S_LEN;
    const int kb0 = kc * KCH;

    const int m0 = (wid >> 2) * 64;
    const int n0 = (wid & 3) * 32;
    const u32 arow = (u32)(lane & 15);
    const u32 csel = (u32)((lane >> 4) << 3);

    float acc[4][4][4];
    #pragma unroll
    for (int mf = 0; mf < 4; mf++)
        #pragma unroll
        for (int nf = 0; nf < 4; nf++)
            #pragma unroll
            for (int r = 0; r < 4; r++) acc[mf][nf][r] = 0.f;

    uint4 pa[2], pb[2];
    auto gload = [&](int c) {
        const int kpos = kb0 + c * 32;
        #pragma unroll
        for (int t = 0; t < 2; t++) {
            int f = tid + 256 * t;
            // A: 128 rows x 32 k (fp16) = 512 uint4
            int row = f >> 2, k8 = (f & 3) * 8;
            pa[t] = *(const uint4*)&Ab[(size_t)row * S_LEN + kpos + k8];
            // B: 32 k-rows x 128 n = 512 uint4
            int kk = f >> 4, n8 = (f & 15) * 8;
            pb[t] = *(const uint4*)&g_wo[(size_t)(kpos + kk) * DM + n8];
        }
    };
    auto sstore = [&](int buf) {
        #pragma unroll
        for (int t = 0; t < 2; t++) {
            int f = tid + 256 * t;
            int row = f >> 2, k8 = (f & 3) * 8;
            *(uint4*)&As2[buf][row * 40 + k8] = pa[t];
            int kk = f >> 4, n8 = (f & 15) * 8;
            *(uint4*)&Bs2[buf][kk * 136 + n8] = pb[t];
        }
    };

    gload(0); sstore(0); __syncthreads();

    int buf = 0;
    for (int c = 0; c < 16; c++) {
        if (c < 15) gload(c + 1);
        #pragma unroll
        for (int kk = 0; kk < 32; kk += 16) {
            u32 a[4][4], bfr[4][2];
            #pragma unroll
            for (int h2 = 0; h2 < 2; h2++) {
                u32 r[4];
                ldsm4t(r, sbm + (u32)buf * (32*136*2) +
                          ((kk + arow) * 136 + n0 + h2 * 16 + csel) * 2);
                bfr[h2*2][0] = r[0];   bfr[h2*2][1] = r[1];
                bfr[h2*2+1][0] = r[2]; bfr[h2*2+1][1] = r[3];
            }
            #pragma unroll
            for (int mf = 0; mf < 4; mf++)
                ldsm4(a[mf], sa + (u32)buf * (128*40*2) +
                             ((m0 + mf * 16 + arow) * 40 + csel + kk) * 2);
            #pragma unroll
            for (int mf = 0; mf < 4; mf++)
                #pragma unroll
                for (int nf = 0; nf < 4; nf++)
                    mma16816(acc[mf][nf], a[mf], bfr[nf]);
        }
        if (c < 15) sstore(buf ^ 1);
        __syncthreads();
        buf ^= 1;
    }

    float* pp = g_part + (size_t)(b * NKC + kc) * DM * DM;
    const int r0 = m0 + (lane >> 2);
    const int cb = n0 + (lane & 3) * 2;
    #pragma unroll
    for (int mf = 0; mf < 4; mf++)
        #pragma unroll
        for (int nf = 0; nf < 4; nf++) {
            int row = r0 + mf * 16, col = cb + nf * 8;
            *(float2*)&pp[row * DM + col] = make_float2(acc[mf][nf][0], acc[mf][nf][1]);
            *(float2*)&pp[(row + 8) * DM + col] = make_float2(acc[mf][nf][2], acc[mf][nf][3]);
        }
}

// ---------------------------------------------------------------------------
// k3: reduce partials + bias (vectorized)
// ---------------------------------------------------------------------------
__global__ void k3_reduce(const float* __restrict__ bout, float* __restrict__ out)
{
    const int i4 = blockIdx.x * 256 + threadIdx.x;   // 0..32767 (float4 index)
    const int b  = i4 >> 12;
    const int rc4 = i4 & 4095;
    float4 s = *(const float4*)&bout[(i4 * 4) & 127];
    const float* p = g_part + (size_t)b * NKC * DM * DM + rc4 * 4;
    #pragma unroll
    for (int kc = 0; kc < NKC; kc++) {
        float4 v = *(const float4*)&p[kc * DM * DM];
        s.x += v.x; s.y += v.y; s.z += v.z; s.w += v.w;
    }
    *(float4*)&out[i4 * 4] = s;
}

// ---------------------------------------------------------------------------
extern "C" void kernel_launch(void* const* d_in, const int* in_sizes, int n_in,
                              void* d_out, int out_size)
{
    const float* x    = (const float*)d_in[0];
    const float* Wqkv = (const float*)d_in[1];
    const float* bqkv = (const float*)d_in[2];
    const float* Wout = (const float*)d_in[3];
    const float* bout = (const float*)d_in[4];
    float* out = (float*)d_out;

    cudaFuncSetAttribute(k1_qkv_attn,
                         cudaFuncAttributeMaxDynamicSharedMemorySize, SM_TOT);

    k0a_convWq<<<(DM * NQKV + 255) / 256, 256>>>(Wqkv);
    k0b_convWo<<<(S_LEN * DM / 4) / 256, 256>>>(Wout);

    k1_qkv_attn<<<(BATCH * S_LEN) / MT1, 256, SM_TOT>>>(x, bqkv);

    dim3 g2(NKC, BATCH);
    k2_partial<<<g2, 256>>>();

    k3_reduce<<<(BATCH * DM * DM / 4) / 256, 256>>>(bout, out);
}